// round 1
// baseline (speedup 1.0000x reference)
#include <cuda_runtime.h>
#include <math.h>

// Problem constants (fixed by the reference)
#define BQ 4
#define TQ 8192
#define DQ 1024
#define CQ 64
#define NCQ 128          // TQ / CQ
#define MQ (BQ*TQ)       // 32768 rows

// Scratch (static device arrays; no allocation allowed)
__device__ float g_v[(size_t)BQ * TQ * DQ];      // proj_write result
__device__ float g_reads[(size_t)BQ * TQ * DQ];  // intra (+ inter accumulated)
__device__ float g_W[(size_t)BQ * DQ * DQ];      // fast-weight scan state

__device__ __forceinline__ float sigmoidf_(float x) { return 1.0f / (1.0f + expf(-x)); }

// ---------------------------------------------------------------------------
// Big GEMM: C = (R ? R + alpha * (A @ B^T) : A @ B^T)
// A: M x K row-major, B: N x K row-major (both K-contiguous).
// 128x128 block tile, 8x8 per-thread microtile, BK=16, double-buffered smem.
// ---------------------------------------------------------------------------
__global__ void __launch_bounds__(256) gemm_abt(
    const float* __restrict__ A,
    const float* __restrict__ Bm,
    const float* __restrict__ R,
    float* __restrict__ C,
    int M, int N, int K,
    const float* __restrict__ log_alpha_ptr)
{
    __shared__ float As[2][16][128];
    __shared__ float Bs[2][16][128];

    const int tid = threadIdx.x;
    const int tx = tid & 15;
    const int ty = tid >> 4;
    const int m0 = blockIdx.y * 128;
    const int n0 = blockIdx.x * 128;
    const int lr = tid >> 2;          // 0..63
    const int lk = (tid & 3) << 2;    // 0,4,8,12

    const float* Ap = A + (size_t)(m0 + lr) * K + lk;
    const float* Bp = Bm + (size_t)(n0 + lr) * K + lk;
    const size_t rstep = (size_t)64 * K;

    float4 a0, a1, b0, b1;
    a0 = *(const float4*)(Ap);
    a1 = *(const float4*)(Ap + rstep);
    b0 = *(const float4*)(Bp);
    b1 = *(const float4*)(Bp + rstep);

    As[0][lk+0][lr] = a0.x; As[0][lk+1][lr] = a0.y; As[0][lk+2][lr] = a0.z; As[0][lk+3][lr] = a0.w;
    As[0][lk+0][64+lr] = a1.x; As[0][lk+1][64+lr] = a1.y; As[0][lk+2][64+lr] = a1.z; As[0][lk+3][64+lr] = a1.w;
    Bs[0][lk+0][lr] = b0.x; Bs[0][lk+1][lr] = b0.y; Bs[0][lk+2][lr] = b0.z; Bs[0][lk+3][lr] = b0.w;
    Bs[0][lk+0][64+lr] = b1.x; Bs[0][lk+1][64+lr] = b1.y; Bs[0][lk+2][64+lr] = b1.z; Bs[0][lk+3][64+lr] = b1.w;
    __syncthreads();

    float acc[8][8];
    #pragma unroll
    for (int i = 0; i < 8; i++)
        #pragma unroll
        for (int j = 0; j < 8; j++) acc[i][j] = 0.0f;

    const int nK = K >> 4;
    int buf = 0;
    for (int kt = 0; kt < nK; kt++) {
        if (kt + 1 < nK) {
            const float* Ap2 = Ap + (size_t)(kt + 1) * 16;
            const float* Bp2 = Bp + (size_t)(kt + 1) * 16;
            a0 = *(const float4*)(Ap2);
            a1 = *(const float4*)(Ap2 + rstep);
            b0 = *(const float4*)(Bp2);
            b1 = *(const float4*)(Bp2 + rstep);
        }
        #pragma unroll
        for (int kk = 0; kk < 16; kk++) {
            float af[8], bf[8];
            *(float4*)(af)     = *(const float4*)&As[buf][kk][ty * 4];
            *(float4*)(af + 4) = *(const float4*)&As[buf][kk][64 + ty * 4];
            *(float4*)(bf)     = *(const float4*)&Bs[buf][kk][tx * 4];
            *(float4*)(bf + 4) = *(const float4*)&Bs[buf][kk][64 + tx * 4];
            #pragma unroll
            for (int i = 0; i < 8; i++)
                #pragma unroll
                for (int j = 0; j < 8; j++)
                    acc[i][j] = fmaf(af[i], bf[j], acc[i][j]);
        }
        if (kt + 1 < nK) {
            buf ^= 1;
            As[buf][lk+0][lr] = a0.x; As[buf][lk+1][lr] = a0.y; As[buf][lk+2][lr] = a0.z; As[buf][lk+3][lr] = a0.w;
            As[buf][lk+0][64+lr] = a1.x; As[buf][lk+1][64+lr] = a1.y; As[buf][lk+2][64+lr] = a1.z; As[buf][lk+3][64+lr] = a1.w;
            Bs[buf][lk+0][lr] = b0.x; Bs[buf][lk+1][lr] = b0.y; Bs[buf][lk+2][lr] = b0.z; Bs[buf][lk+3][lr] = b0.w;
            Bs[buf][lk+0][64+lr] = b1.x; Bs[buf][lk+1][64+lr] = b1.y; Bs[buf][lk+2][64+lr] = b1.z; Bs[buf][lk+3][64+lr] = b1.w;
            __syncthreads();
        }
    }

    float alpha = 1.0f;
    if (log_alpha_ptr) alpha = expf(*log_alpha_ptr);

    #pragma unroll
    for (int i = 0; i < 8; i++) {
        const int m = m0 + ((i < 4) ? (ty * 4 + i) : (64 + ty * 4 + i - 4));
        #pragma unroll
        for (int g = 0; g < 2; g++) {
            const int n = n0 + g * 64 + tx * 4;
            float4 v4;
            v4.x = acc[i][g * 4 + 0];
            v4.y = acc[i][g * 4 + 1];
            v4.z = acc[i][g * 4 + 2];
            v4.w = acc[i][g * 4 + 3];
            if (R) {
                float4 r4 = *(const float4*)&R[(size_t)m * N + n];
                v4.x = fmaf(alpha, v4.x, r4.x);
                v4.y = fmaf(alpha, v4.y, r4.y);
                v4.z = fmaf(alpha, v4.z, r4.z);
                v4.w = fmaf(alpha, v4.w, r4.w);
            }
            *(float4*)&C[(size_t)m * N + n] = v4;
        }
    }
}

// ---------------------------------------------------------------------------
// Intra-chunk kernel (fully parallel over all (b, chunk)):
//   S[c,e] = sum_k r[c,k] * w[e,k]           (K = 1024)
//   P      = S * M                            (causal decay mask)
//   reads[chunk] = P @ v_chunk                (K = 64, writes full 64x1024)
// ---------------------------------------------------------------------------
__global__ void __launch_bounds__(256) intra_kernel(
    const float* __restrict__ out, const float* __restrict__ decay_ptr)
{
    const int j = blockIdx.x;  // chunk index
    const int b = blockIdx.y;
    const float gamma = sigmoidf_(*decay_ptr);
    const float lg = logf(gamma);

    const int tid = threadIdx.x;
    const int tx = tid & 15;
    const int ty = tid >> 4;
    const int lr = tid >> 2;
    const int lk = (tid & 3) << 2;

    __shared__ float SA[16][64];
    __shared__ float SB[16][64];
    __shared__ float Ps[64][64];
    __shared__ float Vs[64][64];

    const float* rbase = out + ((size_t)b * TQ + (size_t)j * CQ) * DQ;
    const int wrow = j * CQ + lr - 1;      // w = out shifted right by one token
    const bool wvalid = (wrow >= 0);
    const float* wptr = out + ((size_t)b * TQ + (size_t)(wvalid ? wrow : 0)) * DQ;

    float acc[4][4];
    #pragma unroll
    for (int i = 0; i < 4; i++)
        #pragma unroll
        for (int jj = 0; jj < 4; jj++) acc[i][jj] = 0.0f;

    // Phase 1: S = r @ w^T over K = 1024
    for (int kt = 0; kt < 64; kt++) {
        __syncthreads();
        float4 ra = *(const float4*)(rbase + (size_t)lr * DQ + kt * 16 + lk);
        float4 wa = make_float4(0.f, 0.f, 0.f, 0.f);
        if (wvalid) wa = *(const float4*)(wptr + kt * 16 + lk);
        SA[lk+0][lr] = ra.x; SA[lk+1][lr] = ra.y; SA[lk+2][lr] = ra.z; SA[lk+3][lr] = ra.w;
        SB[lk+0][lr] = wa.x; SB[lk+1][lr] = wa.y; SB[lk+2][lr] = wa.z; SB[lk+3][lr] = wa.w;
        __syncthreads();
        #pragma unroll
        for (int kk = 0; kk < 16; kk++) {
            float af[4], bf[4];
            *(float4*)af = *(const float4*)&SA[kk][ty * 4];
            *(float4*)bf = *(const float4*)&SB[kk][tx * 4];
            #pragma unroll
            for (int i = 0; i < 4; i++)
                #pragma unroll
                for (int jj = 0; jj < 4; jj++)
                    acc[i][jj] = fmaf(af[i], bf[jj], acc[i][jj]);
        }
    }

    __syncthreads();
    // Apply intra-chunk decay mask: M[c,e] = gamma^(c-1-e) for c > e, else 0
    #pragma unroll
    for (int i = 0; i < 4; i++) {
        #pragma unroll
        for (int jj = 0; jj < 4; jj++) {
            const int c = ty * 4 + i;
            const int e = tx * 4 + jj;
            const float msk = (c > e) ? expf(lg * (float)(c - 1 - e)) : 0.0f;
            Ps[c][e] = acc[i][jj] * msk;
        }
    }

    // Phase 2: reads_chunk = P @ v_chunk (K = 64), sweep d in 16 tiles of 64
    const float* vbase = g_v + ((size_t)b * TQ + (size_t)j * CQ) * DQ;
    float* rd = g_reads + ((size_t)b * TQ + (size_t)j * CQ) * DQ;

    for (int dt = 0; dt < 16; dt++) {
        __syncthreads();
        #pragma unroll
        for (int p = 0; p < 4; p++) {
            const int er = p * 16 + ty;
            *(float4*)&Vs[er][tx * 4] =
                *(const float4*)(vbase + (size_t)er * DQ + dt * 64 + tx * 4);
        }
        __syncthreads();
        float a2[4][4];
        #pragma unroll
        for (int i = 0; i < 4; i++)
            #pragma unroll
            for (int jj = 0; jj < 4; jj++) a2[i][jj] = 0.0f;
        #pragma unroll 16
        for (int e = 0; e < 64; e++) {
            float pf[4], vf[4];
            pf[0] = Ps[ty * 4 + 0][e];
            pf[1] = Ps[ty * 4 + 1][e];
            pf[2] = Ps[ty * 4 + 2][e];
            pf[3] = Ps[ty * 4 + 3][e];
            *(float4*)vf = *(const float4*)&Vs[e][tx * 4];
            #pragma unroll
            for (int i = 0; i < 4; i++)
                #pragma unroll
                for (int jj = 0; jj < 4; jj++)
                    a2[i][jj] = fmaf(pf[i], vf[jj], a2[i][jj]);
        }
        #pragma unroll
        for (int i = 0; i < 4; i++) {
            float4 o;
            o.x = a2[i][0]; o.y = a2[i][1]; o.z = a2[i][2]; o.w = a2[i][3];
            *(float4*)&rd[(size_t)(ty * 4 + i) * DQ + dt * 64 + tx * 4] = o;
        }
    }
}

// ---------------------------------------------------------------------------
// Inter kernel (per chunk t >= 1; reads W *before* update_kernel(t) runs):
//   reads[b, t*C + c, d] += gamma^c * sum_e W[b][d,e] * r[c,e]
// Split-K over e (8 slices of 128) with atomicAdd accumulation.
// Grid: (16 d-tiles, 8 k-slices, 4 batches)
// ---------------------------------------------------------------------------
__global__ void __launch_bounds__(256) inter_kernel(
    const float* __restrict__ out, const float* __restrict__ decay_ptr, int t)
{
    const int dt = blockIdx.x;
    const int ks = blockIdx.y;
    const int b  = blockIdx.z;
    const float gamma = sigmoidf_(*decay_ptr);
    const float lg = logf(gamma);

    const int tid = threadIdx.x;
    const int tx = tid & 15;
    const int ty = tid >> 4;
    const int lr = tid >> 2;
    const int lk = (tid & 3) << 2;

    __shared__ float SA[16][64];  // r   [k][c]
    __shared__ float SB[16][64];  // W   [k][d]

    const float* rbase = out + ((size_t)b * TQ + (size_t)t * CQ) * DQ + ks * 128;
    const float* Wb = g_W + ((size_t)b * DQ + (size_t)dt * 64) * DQ + ks * 128;

    float acc[4][4];
    #pragma unroll
    for (int i = 0; i < 4; i++)
        #pragma unroll
        for (int jj = 0; jj < 4; jj++) acc[i][jj] = 0.0f;

    for (int kt = 0; kt < 8; kt++) {
        __syncthreads();
        float4 ra = *(const float4*)(rbase + (size_t)lr * DQ + kt * 16 + lk);
        float4 wb = *(const float4*)(Wb + (size_t)lr * DQ + kt * 16 + lk);
        SA[lk+0][lr] = ra.x; SA[lk+1][lr] = ra.y; SA[lk+2][lr] = ra.z; SA[lk+3][lr] = ra.w;
        SB[lk+0][lr] = wb.x; SB[lk+1][lr] = wb.y; SB[lk+2][lr] = wb.z; SB[lk+3][lr] = wb.w;
        __syncthreads();
        #pragma unroll
        for (int kk = 0; kk < 16; kk++) {
            float af[4], bf[4];
            *(float4*)af = *(const float4*)&SA[kk][ty * 4];
            *(float4*)bf = *(const float4*)&SB[kk][tx * 4];
            #pragma unroll
            for (int i = 0; i < 4; i++)
                #pragma unroll
                for (int jj = 0; jj < 4; jj++)
                    acc[i][jj] = fmaf(af[i], bf[jj], acc[i][jj]);
        }
    }

    float* rd = g_reads + ((size_t)b * TQ + (size_t)t * CQ) * DQ + dt * 64;
    #pragma unroll
    for (int i = 0; i < 4; i++) {
        const int c = ty * 4 + i;
        const float dec = expf(lg * (float)c);
        #pragma unroll
        for (int jj = 0; jj < 4; jj++)
            atomicAdd(&rd[(size_t)c * DQ + tx * 4 + jj], dec * acc[i][jj]);
    }
}

// ---------------------------------------------------------------------------
// W update kernel (per chunk t):
//   W[b][d,e] = (t>0 ? gamma^C * W[b][d,e] : 0) + sum_c (v[c,d]*gw[c]) * w[c,e]
// Grid: (16 d-tiles, 16 e-tiles, 4 batches); each block owns a 64x64 W tile.
// ---------------------------------------------------------------------------
__global__ void __launch_bounds__(256) update_kernel(
    const float* __restrict__ out, const float* __restrict__ decay_ptr, int t)
{
    const int dt = blockIdx.x;
    const int et = blockIdx.y;
    const int b  = blockIdx.z;
    const float gamma = sigmoidf_(*decay_ptr);
    const float lg = logf(gamma);
    const float gC = expf(lg * (float)CQ);

    const int tid = threadIdx.x;
    const int tx = tid & 15;
    const int ty = tid >> 4;

    __shared__ float Us[64][64];  // (v * gw)[c][d-slab]
    __shared__ float Ws[64][64];  // w[c][e-slab]

    #pragma unroll
    for (int p = 0; p < 4; p++) {
        const int c = p * 16 + ty;
        const float gw = expf(lg * (float)(CQ - 1 - c));
        float4 vv = *(const float4*)(g_v + ((size_t)b * TQ + (size_t)(t * CQ + c)) * DQ + dt * 64 + tx * 4);
        vv.x *= gw; vv.y *= gw; vv.z *= gw; vv.w *= gw;
        *(float4*)&Us[c][tx * 4] = vv;
        const int wrow = t * CQ + c - 1;
        float4 ww = make_float4(0.f, 0.f, 0.f, 0.f);
        if (wrow >= 0)
            ww = *(const float4*)(out + ((size_t)b * TQ + wrow) * DQ + et * 64 + tx * 4);
        *(float4*)&Ws[c][tx * 4] = ww;
    }
    __syncthreads();

    float acc[4][4];
    #pragma unroll
    for (int i = 0; i < 4; i++)
        #pragma unroll
        for (int jj = 0; jj < 4; jj++) acc[i][jj] = 0.0f;

    #pragma unroll 16
    for (int c = 0; c < 64; c++) {
        float uf[4], wf[4];
        *(float4*)uf = *(const float4*)&Us[c][ty * 4];
        *(float4*)wf = *(const float4*)&Ws[c][tx * 4];
        #pragma unroll
        for (int i = 0; i < 4; i++)
            #pragma unroll
            for (int jj = 0; jj < 4; jj++)
                acc[i][jj] = fmaf(uf[i], wf[jj], acc[i][jj]);
    }

    float* Wp = g_W + ((size_t)b * DQ + (size_t)dt * 64) * DQ + et * 64;
    #pragma unroll
    for (int i = 0; i < 4; i++) {
        const int d = ty * 4 + i;
        float4 o;
        o.x = acc[i][0]; o.y = acc[i][1]; o.z = acc[i][2]; o.w = acc[i][3];
        if (t > 0) {
            float4 old = *(const float4*)&Wp[(size_t)d * DQ + tx * 4];
            o.x = fmaf(gC, old.x, o.x);
            o.y = fmaf(gC, old.y, o.y);
            o.z = fmaf(gC, old.z, o.z);
            o.w = fmaf(gC, old.w, o.w);
        }
        *(float4*)&Wp[(size_t)d * DQ + tx * 4] = o;
    }
}

// ---------------------------------------------------------------------------
extern "C" void kernel_launch(void* const* d_in, const int* in_sizes, int n_in,
                              void* d_out, int out_size)
{
    const float* out_in    = (const float*)d_in[0];
    const float* W_write   = (const float*)d_in[1];
    const float* W_read    = (const float*)d_in[2];
    const float* decay     = (const float*)d_in[3];
    const float* log_alpha = (const float*)d_in[4];
    float* outp = (float*)d_out;

    void* pv = nullptr;
    void* pr = nullptr;
    cudaGetSymbolAddress(&pv, g_v);
    cudaGetSymbolAddress(&pr, g_reads);

    // 1) v = out @ W_write^T
    dim3 ggemm(DQ / 128, MQ / 128);  // (8, 256)
    gemm_abt<<<ggemm, 256>>>(out_in, W_write, nullptr, (float*)pv,
                             MQ, DQ, DQ, nullptr);

    // 2) intra-chunk part of reads (all chunks in parallel)
    intra_kernel<<<dim3(NCQ, BQ), 256>>>(out_in, decay);

    // 3) sequential scan over chunks: inter (reads old W) then W update.
    //    Chunk 0: W starts at 0 -> inter is identically zero, skip it;
    //    update_kernel(t=0) does not read W (no zeroing needed between replays).
    for (int t = 0; t < NCQ; t++) {
        if (t > 0)
            inter_kernel<<<dim3(16, 8, BQ), 256>>>(out_in, decay, t);
        update_kernel<<<dim3(16, 16, BQ), 256>>>(out_in, decay, t);
    }

    // 4) output = out + alpha * (reads @ W_read^T)
    gemm_abt<<<ggemm, 256>>>((const float*)pr, W_read, out_in, outp,
                             MQ, DQ, DQ, log_alpha);
}